// round 6
// baseline (speedup 1.0000x reference)
#include <cuda_runtime.h>
#include <cuda_bf16.h>
#include <math.h>
#include <stdint.h>

#define C 128
#define BMAX 4096
#define NMAX 500000

// ---------------- device scratch (no allocations allowed) -------------------
__device__ __align__(16) __nv_bfloat16 g_Wh2[512 * 256];  // reordered folded W, hi split
__device__ __align__(16) __nv_bfloat16 g_Wl2[512 * 256];  // lo split
__device__ __align__(16) __nv_bfloat16 g_W0h[512 * 128];  // reordered W_hh (iter0), hi
__device__ __align__(16) __nv_bfloat16 g_W0l[512 * 128];
__device__ __align__(16) __nv_bfloat16 g_Ah0[BMAX * 128]; // h0 splits (iter0 A)
__device__ __align__(16) __nv_bfloat16 g_Al0[BMAX * 128];
__device__ __align__(16) __nv_bfloat16 g_Xh0[BMAX * 256]; // ping-pong [h | r] hi split
__device__ __align__(16) __nv_bfloat16 g_Xl0[BMAX * 256];
__device__ __align__(16) __nv_bfloat16 g_Xh1[BMAX * 256];
__device__ __align__(16) __nv_bfloat16 g_Xl1[BMAX * 256];
__device__ __align__(16) float g_q[BMAX * 128];           // h (fp32) for attention
__device__ __align__(16) float g_c[BMAX * 128];           // LSTM cell state
__device__ __align__(16) float g_e[NMAX];                 // logits scratch
__device__ __align__(16) float g_bias2[512];              // reordered bias
__device__ int g_seg[BMAX + 1];

__device__ __forceinline__ float sigf(float x) { return 1.0f / (1.0f + __expf(-x)); }

// ---------------- prep: reorder + bf16-split weights, bias ------------------
// Reordered column: col = 4*ch + gate; original row n = gate*C + ch.
// Folded K: k<C adds W_hh (x[:, :C] == h).
__global__ void prep2(const float* __restrict__ Wih, const float* __restrict__ Whh,
                      const float* __restrict__ bih, const float* __restrict__ bhh) {
    int idx = blockIdx.x * blockDim.x + threadIdx.x;   // 512*256
    if (idx >= 512 * 256) return;
    int col = idx >> 8;
    int kk  = idx & 255;
    int gate = col & 3, ch = col >> 2;
    int n = gate * C + ch;
    float w = Wih[n * 256 + kk] + (kk < C ? Whh[n * C + kk] : 0.0f);
    __nv_bfloat16 hi = __float2bfloat16(w);
    g_Wh2[col * 256 + kk] = hi;
    g_Wl2[col * 256 + kk] = __float2bfloat16(w - __bfloat162float(hi));
    if (kk < C) {
        float w0 = Whh[n * C + kk];
        __nv_bfloat16 h0 = __float2bfloat16(w0);
        g_W0h[col * C + kk] = h0;
        g_W0l[col * C + kk] = __float2bfloat16(w0 - __bfloat162float(h0));
    }
    if (kk == 0) g_bias2[col] = bih[n] + bhh[n];
}

__global__ void convert_h0(const float* __restrict__ h, int total) {
    int idx = blockIdx.x * blockDim.x + threadIdx.x;
    if (idx >= total) return;
    float x = h[idx];
    __nv_bfloat16 hi = __float2bfloat16(x);
    g_Ah0[idx] = hi;
    g_Al0[idx] = __float2bfloat16(x - __bfloat162float(hi));
}

// ---------------- segment offsets from sorted batch (int32/int64 probe) -----
__device__ __forceinline__ int bload(const int* p, int i, int is64) {
    return is64 ? p[2 * i] : p[i];
}
__global__ void seg_kernel(const int* __restrict__ batch, int N, int B) {
    int i = blockIdx.x * blockDim.x + threadIdx.x;
    if (i > N) return;
    const int is64 = (batch[N - 1] == 0);
    if (i == 0) {
        int b0 = bload(batch, 0, is64);
        for (int b = 0; b <= b0; b++) g_seg[b] = 0;
    } else if (i == N) {
        int bl = bload(batch, N - 1, is64);
        for (int b = bl + 1; b <= B; b++) g_seg[b] = N;
    } else {
        int bc = bload(batch, i, is64), bp = bload(batch, i - 1, is64);
        for (int b = bp + 1; b <= bc; b++) g_seg[b] = i;
    }
}

// ---------------- mma.sync bf16 GEMM + fused LSTM epilogue ------------------
// D[128 x 256] per CTA = A[128 x K] @ W[256 x K]^T with 3-term bf16 split.
// SMEM operand layout: rows x (64+8) bf16 (pad keeps 16B align, frag LDS conflict-free).
#define KPAD 72
#define OFF_AH 0
#define OFF_AL (128 * KPAD * 2)                 // 18432
#define OFF_BH (2 * 128 * KPAD * 2)             // 36864
#define OFF_BL (OFF_BH + 256 * KPAD * 2)        // 73728
#define PATCH_STRIDE 66                          // floats
#define PATCH_BYTES (64 * PATCH_STRIDE * 4)      // 16896
#define DYN_BYTES (8 * PATCH_BYTES)              // 135168 (covers operands: 110592)

__device__ __forceinline__ void mma16816(float* c, const uint32_t* a, uint32_t b0, uint32_t b1) {
    asm volatile(
        "mma.sync.aligned.m16n8k16.row.col.f32.bf16.bf16.f32 "
        "{%0,%1,%2,%3}, {%4,%5,%6,%7}, {%8,%9}, {%0,%1,%2,%3};"
        : "+f"(c[0]), "+f"(c[1]), "+f"(c[2]), "+f"(c[3])
        : "r"(a[0]), "r"(a[1]), "r"(a[2]), "r"(a[3]), "r"(b0), "r"(b1));
}

__global__ __launch_bounds__(256, 1)
void gemm_fused(const float* __restrict__ h_ext, int first, int NC, int cur, int nxt) {
    extern __shared__ char dyn[];
    __shared__ float sbias[256];

    // resolve scratch pointers IN DEVICE CODE (host-side symbol refs are UB)
    const __nv_bfloat16 *Ah, *Al, *Bh, *Bl;
    if (first)         { Ah = g_Ah0; Al = g_Al0; Bh = g_W0h; Bl = g_W0l; }
    else if (cur == 0) { Ah = g_Xh0; Al = g_Xl0; Bh = g_Wh2; Bl = g_Wl2; }
    else               { Ah = g_Xh1; Al = g_Xl1; Bh = g_Wh2; Bl = g_Wl2; }
    __nv_bfloat16* XhO = nxt ? g_Xh1 : g_Xh0;   // next-iteration input buffer
    __nv_bfloat16* XlO = nxt ? g_Xl1 : g_Xl0;

    const int tid = threadIdx.x, wid = tid >> 5, lane = tid & 31;
    const int g = lane >> 2, t = lane & 3;
    const int bn = blockIdx.x;             // 0..1 (256 reordered cols each)
    const int bm = blockIdx.y;
    const int m0 = bm * 128;
    const int wm = (wid >> 2) * 64;        // warp tile origin in CTA
    const int wn = (wid & 3) * 64;

    if (tid < 256) sbias[tid] = g_bias2[bn * 256 + tid];

    const int strideK = NC * 64;
    const __nv_bfloat16* Abh = Ah + (size_t)m0 * strideK;
    const __nv_bfloat16* Abl = Al + (size_t)m0 * strideK;
    const __nv_bfloat16* Bbh = Bh + (size_t)(bn * 256) * strideK;
    const __nv_bfloat16* Bbl = Bl + (size_t)(bn * 256) * strideK;

    float acc[4][8][4];
#pragma unroll
    for (int mi = 0; mi < 4; mi++)
#pragma unroll
        for (int ni = 0; ni < 8; ni++)
#pragma unroll
            for (int e = 0; e < 4; e++) acc[mi][ni][e] = 0.0f;

    for (int cch = 0; cch < NC; cch++) {
        __syncthreads();   // previous chunk fully consumed before overwrite
        // A tiles: 128 rows x 64 bf16 per split
#pragma unroll
        for (int i = tid; i < 1024; i += 256) {
            int row = i >> 3, seg = i & 7;
            int dst = row * (KPAD * 2) + seg * 16;
            const size_t src = (size_t)row * strideK + cch * 64 + seg * 8;
            *(uint4*)(dyn + OFF_AH + dst) = *(const uint4*)(Abh + src);
            *(uint4*)(dyn + OFF_AL + dst) = *(const uint4*)(Abl + src);
        }
        // B tiles: 256 rows x 64 bf16 per split
#pragma unroll
        for (int i = tid; i < 2048; i += 256) {
            int row = i >> 3, seg = i & 7;
            int dst = row * (KPAD * 2) + seg * 16;
            const size_t src = (size_t)row * strideK + cch * 64 + seg * 8;
            *(uint4*)(dyn + OFF_BH + dst) = *(const uint4*)(Bbh + src);
            *(uint4*)(dyn + OFF_BL + dst) = *(const uint4*)(Bbl + src);
        }
        __syncthreads();

#pragma unroll
        for (int ks = 0; ks < 4; ks++) {
            uint32_t ah[4][4], al[4][4];
            const int kb = ks * 32 + t * 4;            // byte offset of k=ks*16+2t
#pragma unroll
            for (int mi = 0; mi < 4; mi++) {
                int r0 = (wm + mi * 16 + g) * (KPAD * 2) + kb;
                int r1 = r0 + 8 * (KPAD * 2);
                ah[mi][0] = *(const uint32_t*)(dyn + OFF_AH + r0);
                ah[mi][1] = *(const uint32_t*)(dyn + OFF_AH + r1);
                ah[mi][2] = *(const uint32_t*)(dyn + OFF_AH + r0 + 16);
                ah[mi][3] = *(const uint32_t*)(dyn + OFF_AH + r1 + 16);
                al[mi][0] = *(const uint32_t*)(dyn + OFF_AL + r0);
                al[mi][1] = *(const uint32_t*)(dyn + OFF_AL + r1);
                al[mi][2] = *(const uint32_t*)(dyn + OFF_AL + r0 + 16);
                al[mi][3] = *(const uint32_t*)(dyn + OFF_AL + r1 + 16);
            }
#pragma unroll
            for (int ni = 0; ni < 8; ni++) {
                int nrow = (wn + ni * 8 + g) * (KPAD * 2) + kb;
                uint32_t bh0 = *(const uint32_t*)(dyn + OFF_BH + nrow);
                uint32_t bh1 = *(const uint32_t*)(dyn + OFF_BH + nrow + 16);
                uint32_t bl0 = *(const uint32_t*)(dyn + OFF_BL + nrow);
                uint32_t bl1 = *(const uint32_t*)(dyn + OFF_BL + nrow + 16);
#pragma unroll
                for (int mi = 0; mi < 4; mi++) {
                    mma16816(acc[mi][ni], ah[mi], bh0, bh1);
                    mma16816(acc[mi][ni], al[mi], bh0, bh1);
                    mma16816(acc[mi][ni], ah[mi], bl0, bl1);
                }
            }
        }
    }
    __syncthreads();   // all warps done reading operands; reuse smem for acc dump

    // ---- dump acc to per-warp patch [64][66] floats ----
    float* patch = (float*)(dyn + wid * PATCH_BYTES);
#pragma unroll
    for (int mi = 0; mi < 4; mi++)
#pragma unroll
        for (int ni = 0; ni < 8; ni++) {
            int pr = mi * 16 + g, pc = ni * 8 + 2 * t;
            *(float2*)&patch[pr * PATCH_STRIDE + pc]       = make_float2(acc[mi][ni][0], acc[mi][ni][1]);
            *(float2*)&patch[(pr + 8) * PATCH_STRIDE + pc] = make_float2(acc[mi][ni][2], acc[mi][ni][3]);
        }
    __syncthreads();

    // ---- fused LSTM: 128 rows x 64 channels per CTA ----
#pragma unroll
    for (int it = 0; it < 32; it++) {
        int item = tid + it * 256;          // 8192 items
        int r = item >> 6, chl = item & 63;
        int w = (r >> 6) * 4 + (chl >> 4);
        const float* p = (const float*)(dyn + w * PATCH_BYTES)
                         + (r & 63) * PATCH_STRIDE + (chl & 15) * 4;
        int cb = chl * 4;
        float gi = p[0] + sbias[cb + 0];
        float gf = p[1] + sbias[cb + 1];
        float gg = p[2] + sbias[cb + 2];
        float go = p[3] + sbias[cb + 3];
        int row = m0 + r;
        int ch = bn * 64 + chl;
        size_t cidx = (size_t)row * C + ch;
        float cp = first ? h_ext[cidx] : g_c[cidx];
        float cn = sigf(gf) * cp + sigf(gi) * tanhf(gg);
        g_c[cidx] = cn;
        float hn = sigf(go) * tanhf(cn);
        g_q[cidx] = hn;
        __nv_bfloat16 hh = __float2bfloat16(hn);
        XhO[(size_t)row * 256 + ch] = hh;
        XlO[(size_t)row * 256 + ch] = __float2bfloat16(hn - __bfloat162float(hh));
    }
}

// ---------------- segment attention: one block per segment ------------------
__global__ __launch_bounds__(256)
void attn_kernel(const float* __restrict__ kmat, const float* __restrict__ vmat,
                 float* __restrict__ out, int iter, int nxt) {
    int b = blockIdx.x;
    int tid = threadIdx.x;
    int lane = tid & 31;
    int w = tid >> 5;                       // 8 warps
    int start = g_seg[b], end = g_seg[b + 1];

    __nv_bfloat16* XhO = nxt ? g_Xh1 : g_Xh0;
    __nv_bfloat16* XlO = nxt ? g_Xl1 : g_Xl0;

    float4 q4 = *(const float4*)(g_q + (size_t)b * C + lane * 4);

    __shared__ float smax[8];
    __shared__ float ssum[8];
    __shared__ __align__(16) float sr[8][C];

    // pass 1: logits + max
    float wmax = -INFINITY;
    int node = start + w;
    for (; node + 8 < end; node += 16) {
        float4 ka = *(const float4*)(kmat + (size_t)node * C + lane * 4);
        float4 kb = *(const float4*)(kmat + (size_t)(node + 8) * C + lane * 4);
        float da = ka.x * q4.x + ka.y * q4.y + ka.z * q4.z + ka.w * q4.w;
        float db = kb.x * q4.x + kb.y * q4.y + kb.z * q4.z + kb.w * q4.w;
#pragma unroll
        for (int off = 16; off > 0; off >>= 1) {
            da += __shfl_xor_sync(0xFFFFFFFFu, da, off);
            db += __shfl_xor_sync(0xFFFFFFFFu, db, off);
        }
        if (lane == 0) { g_e[node] = da; g_e[node + 8] = db; }
        wmax = fmaxf(wmax, fmaxf(da, db));
    }
    for (; node < end; node += 8) {
        float4 ka = *(const float4*)(kmat + (size_t)node * C + lane * 4);
        float da = ka.x * q4.x + ka.y * q4.y + ka.z * q4.z + ka.w * q4.w;
#pragma unroll
        for (int off = 16; off > 0; off >>= 1)
            da += __shfl_xor_sync(0xFFFFFFFFu, da, off);
        if (lane == 0) g_e[node] = da;
        wmax = fmaxf(wmax, da);
    }
    if (lane == 0) smax[w] = wmax;
    __syncthreads();

    float m = -INFINITY;
#pragma unroll
    for (int i = 0; i < 8; i++) m = fmaxf(m, smax[i]);

    // pass 2: exp + weighted V sum
    float s = 0.0f;
    float4 r4 = make_float4(0.f, 0.f, 0.f, 0.f);
    for (node = start + w; node < end; node += 8) {
        float a = __expf(g_e[node] - m);
        float4 v4 = *(const float4*)(vmat + (size_t)node * C + lane * 4);
        s += a;
        r4.x = fmaf(a, v4.x, r4.x); r4.y = fmaf(a, v4.y, r4.y);
        r4.z = fmaf(a, v4.z, r4.z); r4.w = fmaf(a, v4.w, r4.w);
    }
    if (lane == 0) ssum[w] = s;
    *(float4*)(&sr[w][lane * 4]) = r4;
    __syncthreads();

    if (tid < C) {
        float stot = 0.0f, rc = 0.0f;
#pragma unroll
        for (int i = 0; i < 8; i++) { stot += ssum[i]; rc += sr[i][tid]; }
        float val = rc / (stot + 1e-16f);
        out[(size_t)b * 4 * C + iter * C + tid] = val;       // readout
        __nv_bfloat16 hv = __float2bfloat16(val);            // r splits for next GEMM
        XhO[(size_t)b * 256 + C + tid] = hv;
        XlO[(size_t)b * 256 + C + tid] = __float2bfloat16(val - __bfloat162float(hv));
    }
}

// ---------------- launch -----------------------------------------------------
extern "C" void kernel_launch(void* const* d_in, const int* in_sizes, int n_in,
                              void* d_out, int out_size) {
    const float* k     = (const float*)d_in[0];
    const float* v     = (const float*)d_in[1];
    const float* h     = (const float*)d_in[2];
    const float* W_ih  = (const float*)d_in[3];
    const float* W_hh  = (const float*)d_in[4];
    const float* b_ih  = (const float*)d_in[5];
    const float* b_hh  = (const float*)d_in[6];
    const int*   batch = (const int*)d_in[7];
    float* out = (float*)d_out;

    int N = in_sizes[0] / C;
    int B = in_sizes[2] / C;

    cudaFuncSetAttribute(gemm_fused, cudaFuncAttributeMaxDynamicSharedMemorySize, DYN_BYTES);

    prep2<<<(512 * 256 + 255) / 256, 256>>>(W_ih, W_hh, b_ih, b_hh);
    convert_h0<<<(B * C + 255) / 256, 256>>>(h, B * C);
    seg_kernel<<<(N + 256) / 256, 256>>>(batch, N, B);

    for (int t = 0; t < 4; t++) {
        int cur = t & 1, nxt = (t + 1) & 1;
        gemm_fused<<<dim3(2, B / 128), 256, DYN_BYTES>>>(
            h, t == 0 ? 1 : 0, t == 0 ? 2 : 4, cur, nxt);
        attn_kernel<<<B, 256>>>(k, v, out, t, nxt);
    }
}

// round 7
// speedup vs baseline: 1.1305x; 1.1305x over previous
#include <cuda_runtime.h>
#include <cuda_bf16.h>
#include <math.h>
#include <stdint.h>

#define C 128
#define BMAX 4096
#define NMAX 500000

// ---------------- device scratch (no allocations allowed) -------------------
__device__ __align__(16) __nv_bfloat16 g_Wh2[512 * 256];  // reordered folded W, hi split
__device__ __align__(16) __nv_bfloat16 g_Wl2[512 * 256];  // lo split
__device__ __align__(16) __nv_bfloat16 g_W0h[512 * 128];  // reordered W_hh (iter0), hi
__device__ __align__(16) __nv_bfloat16 g_W0l[512 * 128];
__device__ __align__(16) __nv_bfloat16 g_Ah0[BMAX * 128]; // h0 splits (iter0 A)
__device__ __align__(16) __nv_bfloat16 g_Al0[BMAX * 128];
__device__ __align__(16) __nv_bfloat16 g_Xh0[BMAX * 256]; // ping-pong [h | r] hi split
__device__ __align__(16) __nv_bfloat16 g_Xl0[BMAX * 256];
__device__ __align__(16) __nv_bfloat16 g_Xh1[BMAX * 256];
__device__ __align__(16) __nv_bfloat16 g_Xl1[BMAX * 256];
__device__ __align__(16) float g_q[BMAX * 128];           // h (fp32) for attention
__device__ __align__(16) float g_c[BMAX * 128];           // LSTM cell state
__device__ __align__(16) float g_e[NMAX];                 // logits scratch
__device__ __align__(16) float g_bias2[512];              // reordered bias
__device__ int g_seg[BMAX + 1];

__device__ __forceinline__ float sigf(float x) { return 1.0f / (1.0f + __expf(-x)); }

// ---------------- prep: reorder + bf16-split weights, bias ------------------
__global__ void prep2(const float* __restrict__ Wih, const float* __restrict__ Whh,
                      const float* __restrict__ bih, const float* __restrict__ bhh) {
    int idx = blockIdx.x * blockDim.x + threadIdx.x;   // 512*256
    if (idx >= 512 * 256) return;
    int col = idx >> 8;
    int kk  = idx & 255;
    int gate = col & 3, ch = col >> 2;
    int n = gate * C + ch;
    float w = Wih[n * 256 + kk] + (kk < C ? Whh[n * C + kk] : 0.0f);
    __nv_bfloat16 hi = __float2bfloat16(w);
    g_Wh2[col * 256 + kk] = hi;
    g_Wl2[col * 256 + kk] = __float2bfloat16(w - __bfloat162float(hi));
    if (kk < C) {
        float w0 = Whh[n * C + kk];
        __nv_bfloat16 h0 = __float2bfloat16(w0);
        g_W0h[col * C + kk] = h0;
        g_W0l[col * C + kk] = __float2bfloat16(w0 - __bfloat162float(h0));
    }
    if (kk == 0) g_bias2[col] = bih[n] + bhh[n];
}

__global__ void convert_h0(const float* __restrict__ h, int total) {
    int idx = blockIdx.x * blockDim.x + threadIdx.x;
    if (idx >= total) return;
    float x = h[idx];
    __nv_bfloat16 hi = __float2bfloat16(x);
    g_Ah0[idx] = hi;
    g_Al0[idx] = __float2bfloat16(x - __bfloat162float(hi));
}

// ---------------- segment offsets from sorted batch (int32/int64 probe) -----
__device__ __forceinline__ int bload(const int* p, int i, int is64) {
    return is64 ? p[2 * i] : p[i];
}
__global__ void seg_kernel(const int* __restrict__ batch, int N, int B) {
    int i = blockIdx.x * blockDim.x + threadIdx.x;
    if (i > N) return;
    const int is64 = (batch[N - 1] == 0);
    if (i == 0) {
        int b0 = bload(batch, 0, is64);
        for (int b = 0; b <= b0; b++) g_seg[b] = 0;
    } else if (i == N) {
        int bl = bload(batch, N - 1, is64);
        for (int b = bl + 1; b <= B; b++) g_seg[b] = N;
    } else {
        int bc = bload(batch, i, is64), bp = bload(batch, i - 1, is64);
        for (int b = bp + 1; b <= bc; b++) g_seg[b] = i;
    }
}

// ---------------- mma.sync bf16 GEMM + fused LSTM epilogue ------------------
// D[128 x 128] per CTA = A[128 x K] @ W[128 x K]^T, 3-term bf16 split.
// Warp tile 32x64 (acc 64 regs). Grid (4, B/128) = 128 CTAs.
#define KPAD 72
#define OFF_AH 0
#define OFF_AL (128 * KPAD * 2)                 // 18432
#define OFF_BH (2 * 128 * KPAD * 2)             // 36864
#define OFF_BL (OFF_BH + 128 * KPAD * 2)        // 55296
#define DYN_BYTES (OFF_BL + 128 * KPAD * 2)     // 73728
#define PATCH_STRIDE 68                          // floats; 272B row (16B-mult)
#define PATCH_BYTES (32 * PATCH_STRIDE * 4)      // 8704; x8 warps = 69632 < 73728

__device__ __forceinline__ void mma16816(float* c, const uint32_t* a, uint32_t b0, uint32_t b1) {
    asm volatile(
        "mma.sync.aligned.m16n8k16.row.col.f32.bf16.bf16.f32 "
        "{%0,%1,%2,%3}, {%4,%5,%6,%7}, {%8,%9}, {%0,%1,%2,%3};"
        : "+f"(c[0]), "+f"(c[1]), "+f"(c[2]), "+f"(c[3])
        : "r"(a[0]), "r"(a[1]), "r"(a[2]), "r"(a[3]), "r"(b0), "r"(b1));
}

__global__ __launch_bounds__(256, 2)
void gemm_fused(const float* __restrict__ h_ext, int first, int NC, int cur, int nxt) {
    extern __shared__ char dyn[];
    __shared__ float sbias[128];

    // resolve scratch pointers IN DEVICE CODE (host-side symbol refs are UB)
    const __nv_bfloat16 *Ah, *Al, *Bh, *Bl;
    if (first)         { Ah = g_Ah0; Al = g_Al0; Bh = g_W0h; Bl = g_W0l; }
    else if (cur == 0) { Ah = g_Xh0; Al = g_Xl0; Bh = g_Wh2; Bl = g_Wl2; }
    else               { Ah = g_Xh1; Al = g_Xl1; Bh = g_Wh2; Bl = g_Wl2; }
    __nv_bfloat16* XhO = nxt ? g_Xh1 : g_Xh0;   // next-iteration input buffer
    __nv_bfloat16* XlO = nxt ? g_Xl1 : g_Xl0;

    const int tid = threadIdx.x, wid = tid >> 5, lane = tid & 31;
    const int g = lane >> 2, t = lane & 3;
    const int bn = blockIdx.x;             // 0..3 (128 reordered cols = 32 channels)
    const int bm = blockIdx.y;
    const int m0 = bm * 128;
    const int wm = (wid >> 1) * 32;        // warp tile origin: 4 m-groups x 2 n-groups
    const int wn = (wid & 1) * 64;

    if (tid < 128) sbias[tid] = g_bias2[bn * 128 + tid];

    const int strideK = NC * 64;
    const __nv_bfloat16* Abh = Ah + (size_t)m0 * strideK;
    const __nv_bfloat16* Abl = Al + (size_t)m0 * strideK;
    const __nv_bfloat16* Bbh = Bh + (size_t)(bn * 128) * strideK;
    const __nv_bfloat16* Bbl = Bl + (size_t)(bn * 128) * strideK;

    float acc[2][8][4];
#pragma unroll
    for (int mi = 0; mi < 2; mi++)
#pragma unroll
        for (int ni = 0; ni < 8; ni++)
#pragma unroll
            for (int e = 0; e < 4; e++) acc[mi][ni][e] = 0.0f;

    for (int cch = 0; cch < NC; cch++) {
        __syncthreads();   // previous chunk fully consumed before overwrite
        // A and B tiles: 128 rows x 64 bf16 per split each
#pragma unroll
        for (int i = tid; i < 1024; i += 256) {
            int row = i >> 3, seg = i & 7;
            int dst = row * (KPAD * 2) + seg * 16;
            const size_t srcA = (size_t)row * strideK + cch * 64 + seg * 8;
            *(uint4*)(dyn + OFF_AH + dst) = *(const uint4*)(Abh + srcA);
            *(uint4*)(dyn + OFF_AL + dst) = *(const uint4*)(Abl + srcA);
            *(uint4*)(dyn + OFF_BH + dst) = *(const uint4*)(Bbh + srcA);
            *(uint4*)(dyn + OFF_BL + dst) = *(const uint4*)(Bbl + srcA);
        }
        __syncthreads();

#pragma unroll
        for (int ks = 0; ks < 4; ks++) {
            uint32_t ah[2][4], al[2][4];
            const int kb = ks * 32 + t * 4;            // byte offset of k=ks*16+2t
#pragma unroll
            for (int mi = 0; mi < 2; mi++) {
                int r0 = (wm + mi * 16 + g) * (KPAD * 2) + kb;
                int r1 = r0 + 8 * (KPAD * 2);
                ah[mi][0] = *(const uint32_t*)(dyn + OFF_AH + r0);
                ah[mi][1] = *(const uint32_t*)(dyn + OFF_AH + r1);
                ah[mi][2] = *(const uint32_t*)(dyn + OFF_AH + r0 + 16);
                ah[mi][3] = *(const uint32_t*)(dyn + OFF_AH + r1 + 16);
                al[mi][0] = *(const uint32_t*)(dyn + OFF_AL + r0);
                al[mi][1] = *(const uint32_t*)(dyn + OFF_AL + r1);
                al[mi][2] = *(const uint32_t*)(dyn + OFF_AL + r0 + 16);
                al[mi][3] = *(const uint32_t*)(dyn + OFF_AL + r1 + 16);
            }
#pragma unroll
            for (int ni = 0; ni < 8; ni++) {
                int nrow = (wn + ni * 8 + g) * (KPAD * 2) + kb;
                uint32_t bh0 = *(const uint32_t*)(dyn + OFF_BH + nrow);
                uint32_t bh1 = *(const uint32_t*)(dyn + OFF_BH + nrow + 16);
                uint32_t bl0 = *(const uint32_t*)(dyn + OFF_BL + nrow);
                uint32_t bl1 = *(const uint32_t*)(dyn + OFF_BL + nrow + 16);
#pragma unroll
                for (int mi = 0; mi < 2; mi++) {
                    mma16816(acc[mi][ni], ah[mi], bh0, bh1);
                    mma16816(acc[mi][ni], al[mi], bh0, bh1);
                    mma16816(acc[mi][ni], ah[mi], bl0, bl1);
                }
            }
        }
    }
    __syncthreads();   // operands consumed; reuse smem for acc patches

    // ---- dump acc to per-warp patch [32][68] floats ----
    float* patch = (float*)(dyn + wid * PATCH_BYTES);
#pragma unroll
    for (int mi = 0; mi < 2; mi++)
#pragma unroll
        for (int ni = 0; ni < 8; ni++) {
            int pr = mi * 16 + g, pc = ni * 8 + 2 * t;
            *(float2*)&patch[pr * PATCH_STRIDE + pc]       = make_float2(acc[mi][ni][0], acc[mi][ni][1]);
            *(float2*)&patch[(pr + 8) * PATCH_STRIDE + pc] = make_float2(acc[mi][ni][2], acc[mi][ni][3]);
        }
    __syncthreads();

    // ---- fused LSTM: 128 rows x 32 channels per CTA = 4096 items ----
#pragma unroll
    for (int it = 0; it < 16; it++) {
        int item = tid + it * 256;
        int r = item >> 5, chl = item & 31;
        int w = (r >> 5) * 2 + (chl >> 4);    // source warp patch
        const float* p = (const float*)(dyn + w * PATCH_BYTES)
                         + (r & 31) * PATCH_STRIDE + (chl & 15) * 4;
        float4 gv = *(const float4*)p;
        int cb = chl * 4;
        float gi = gv.x + sbias[cb + 0];
        float gf = gv.y + sbias[cb + 1];
        float gg = gv.z + sbias[cb + 2];
        float go = gv.w + sbias[cb + 3];
        int row = m0 + r;
        int ch = bn * 32 + chl;
        size_t cidx = (size_t)row * C + ch;
        float cp = first ? h_ext[cidx] : g_c[cidx];
        float cn = sigf(gf) * cp + sigf(gi) * tanhf(gg);
        g_c[cidx] = cn;
        float hn = sigf(go) * tanhf(cn);
        g_q[cidx] = hn;
        __nv_bfloat16 hh = __float2bfloat16(hn);
        XhO[(size_t)row * 256 + ch] = hh;
        XlO[(size_t)row * 256 + ch] = __float2bfloat16(hn - __bfloat162float(hh));
    }
}

// ---------------- segment attention: one block per segment ------------------
__global__ __launch_bounds__(256)
void attn_kernel(const float* __restrict__ kmat, const float* __restrict__ vmat,
                 float* __restrict__ out, int iter, int nxt) {
    int b = blockIdx.x;
    int tid = threadIdx.x;
    int lane = tid & 31;
    int w = tid >> 5;                       // 8 warps
    int start = g_seg[b], end = g_seg[b + 1];

    __nv_bfloat16* XhO = nxt ? g_Xh1 : g_Xh0;
    __nv_bfloat16* XlO = nxt ? g_Xl1 : g_Xl0;

    float4 q4 = *(const float4*)(g_q + (size_t)b * C + lane * 4);

    __shared__ float smax[8];
    __shared__ float ssum[8];
    __shared__ __align__(16) float sr[8][C];

    // pass 1: logits + max
    float wmax = -INFINITY;
    int node = start + w;
    for (; node + 8 < end; node += 16) {
        float4 ka = *(const float4*)(kmat + (size_t)node * C + lane * 4);
        float4 kb = *(const float4*)(kmat + (size_t)(node + 8) * C + lane * 4);
        float da = ka.x * q4.x + ka.y * q4.y + ka.z * q4.z + ka.w * q4.w;
        float db = kb.x * q4.x + kb.y * q4.y + kb.z * q4.z + kb.w * q4.w;
#pragma unroll
        for (int off = 16; off > 0; off >>= 1) {
            da += __shfl_xor_sync(0xFFFFFFFFu, da, off);
            db += __shfl_xor_sync(0xFFFFFFFFu, db, off);
        }
        if (lane == 0) { g_e[node] = da; g_e[node + 8] = db; }
        wmax = fmaxf(wmax, fmaxf(da, db));
    }
    for (; node < end; node += 8) {
        float4 ka = *(const float4*)(kmat + (size_t)node * C + lane * 4);
        float da = ka.x * q4.x + ka.y * q4.y + ka.z * q4.z + ka.w * q4.w;
#pragma unroll
        for (int off = 16; off > 0; off >>= 1)
            da += __shfl_xor_sync(0xFFFFFFFFu, da, off);
        if (lane == 0) g_e[node] = da;
        wmax = fmaxf(wmax, da);
    }
    if (lane == 0) smax[w] = wmax;
    __syncthreads();

    float m = -INFINITY;
#pragma unroll
    for (int i = 0; i < 8; i++) m = fmaxf(m, smax[i]);

    // pass 2: exp + weighted V sum
    float s = 0.0f;
    float4 r4 = make_float4(0.f, 0.f, 0.f, 0.f);
    for (node = start + w; node < end; node += 8) {
        float a = __expf(g_e[node] - m);
        float4 v4 = *(const float4*)(vmat + (size_t)node * C + lane * 4);
        s += a;
        r4.x = fmaf(a, v4.x, r4.x); r4.y = fmaf(a, v4.y, r4.y);
        r4.z = fmaf(a, v4.z, r4.z); r4.w = fmaf(a, v4.w, r4.w);
    }
    if (lane == 0) ssum[w] = s;
    *(float4*)(&sr[w][lane * 4]) = r4;
    __syncthreads();

    if (tid < C) {
        float stot = 0.0f, rc = 0.0f;
#pragma unroll
        for (int i = 0; i < 8; i++) { stot += ssum[i]; rc += sr[i][tid]; }
        float val = rc / (stot + 1e-16f);
        out[(size_t)b * 4 * C + iter * C + tid] = val;       // readout
        __nv_bfloat16 hv = __float2bfloat16(val);            // r splits for next GEMM
        XhO[(size_t)b * 256 + C + tid] = hv;
        XlO[(size_t)b * 256 + C + tid] = __float2bfloat16(val - __bfloat162float(hv));
    }
}

// ---------------- launch -----------------------------------------------------
extern "C" void kernel_launch(void* const* d_in, const int* in_sizes, int n_in,
                              void* d_out, int out_size) {
    const float* k     = (const float*)d_in[0];
    const float* v     = (const float*)d_in[1];
    const float* h     = (const float*)d_in[2];
    const float* W_ih  = (const float*)d_in[3];
    const float* W_hh  = (const float*)d_in[4];
    const float* b_ih  = (const float*)d_in[5];
    const float* b_hh  = (const float*)d_in[6];
    const int*   batch = (const int*)d_in[7];
    float* out = (float*)d_out;

    int N = in_sizes[0] / C;
    int B = in_sizes[2] / C;

    cudaFuncSetAttribute(gemm_fused, cudaFuncAttributeMaxDynamicSharedMemorySize, DYN_BYTES);

    prep2<<<(512 * 256 + 255) / 256, 256>>>(W_ih, W_hh, b_ih, b_hh);
    convert_h0<<<(B * C + 255) / 256, 256>>>(h, B * C);
    seg_kernel<<<(N + 256) / 256, 256>>>(batch, N, B);

    for (int t = 0; t < 4; t++) {
        int cur = t & 1, nxt = (t + 1) & 1;
        gemm_fused<<<dim3(4, B / 128), 256, DYN_BYTES>>>(
            h, t == 0 ? 1 : 0, t == 0 ? 2 : 4, cur, nxt);
        attn_kernel<<<B, 256>>>(k, v, out, t, nxt);
    }
}

// round 8
// speedup vs baseline: 1.1703x; 1.0353x over previous
#include <cuda_runtime.h>
#include <cuda_bf16.h>
#include <math.h>
#include <stdint.h>

#define C 128
#define BMAX 4096
#define NMAX 500000

// ---------------- device scratch (no allocations allowed) -------------------
__device__ __align__(16) __nv_bfloat16 g_Wh2[512 * 256];  // reordered folded W, hi split
__device__ __align__(16) __nv_bfloat16 g_Wl2[512 * 256];  // lo split
__device__ __align__(16) __nv_bfloat16 g_W0h[512 * 128];  // reordered W_hh (iter0), hi
__device__ __align__(16) __nv_bfloat16 g_W0l[512 * 128];
__device__ __align__(16) __nv_bfloat16 g_Ah0[BMAX * 128]; // h0 splits (iter0 A)
__device__ __align__(16) __nv_bfloat16 g_Al0[BMAX * 128];
__device__ __align__(16) __nv_bfloat16 g_Xh0[BMAX * 256]; // ping-pong [h | r] hi split
__device__ __align__(16) __nv_bfloat16 g_Xl0[BMAX * 256];
__device__ __align__(16) __nv_bfloat16 g_Xh1[BMAX * 256];
__device__ __align__(16) __nv_bfloat16 g_Xl1[BMAX * 256];
__device__ __align__(16) float g_q[BMAX * 128];           // h (fp32) for attention
__device__ __align__(16) float g_c[BMAX * 128];           // LSTM cell state
__device__ __align__(16) float g_e[NMAX];                 // logits scratch
__device__ __align__(16) float g_bias2[512];              // reordered bias
__device__ int g_seg[BMAX + 1];

__device__ __forceinline__ float sigf(float x) { return 1.0f / (1.0f + __expf(-x)); }

// ---------------- merged prep: weights + h0 convert + seg offsets ----------
__device__ __forceinline__ int bload(const int* p, int i, int is64) {
    return is64 ? p[2 * i] : p[i];
}
__global__ void prep_all(const float* __restrict__ Wih, const float* __restrict__ Whh,
                         const float* __restrict__ bih, const float* __restrict__ bhh,
                         const float* __restrict__ h, const int* __restrict__ batch,
                         int N, int B) {
    int idx = blockIdx.x * blockDim.x + threadIdx.x;

    if (idx < 512 * 256) {       // weights: col = 4*ch + gate; n = gate*C + ch
        int col = idx >> 8;
        int kk  = idx & 255;
        int gate = col & 3, ch = col >> 2;
        int n = gate * C + ch;
        float w = Wih[n * 256 + kk] + (kk < C ? Whh[n * C + kk] : 0.0f);
        __nv_bfloat16 hi = __float2bfloat16(w);
        g_Wh2[col * 256 + kk] = hi;
        g_Wl2[col * 256 + kk] = __float2bfloat16(w - __bfloat162float(hi));
        if (kk < C) {
            float w0 = Whh[n * C + kk];
            __nv_bfloat16 h0 = __float2bfloat16(w0);
            g_W0h[col * C + kk] = h0;
            g_W0l[col * C + kk] = __float2bfloat16(w0 - __bfloat162float(h0));
        }
        if (kk == 0) g_bias2[col] = bih[n] + bhh[n];
    }
    if (idx < B * C) {           // h0 -> bf16 splits
        float x = h[idx];
        __nv_bfloat16 hi = __float2bfloat16(x);
        g_Ah0[idx] = hi;
        g_Al0[idx] = __float2bfloat16(x - __bfloat162float(hi));
    }
    if (idx <= N) {              // segment offsets (int32/int64 probe)
        const int is64 = (batch[N - 1] == 0);
        if (idx == 0) {
            int b0 = bload(batch, 0, is64);
            for (int b = 0; b <= b0; b++) g_seg[b] = 0;
        } else if (idx == N) {
            int bl = bload(batch, N - 1, is64);
            for (int b = bl + 1; b <= B; b++) g_seg[b] = N;
        } else {
            int bc = bload(batch, idx, is64), bp = bload(batch, idx - 1, is64);
            for (int b = bp + 1; b <= bc; b++) g_seg[b] = idx;
        }
    }
}

// ---------------- mma.sync bf16 GEMM + fused LSTM epilogue ------------------
// CTA tile: 64(M) x 128(N), 128 threads (4 warps, warp tile 32x64).
// K chunked by 64, 2-stage cp.async pipeline. 3-term bf16 split.
#define KPAD 72                                  // smem row = 144 B
#define A_SPLIT (64 * KPAD * 2)                  // 9216
#define B_SPLIT (128 * KPAD * 2)                 // 18432
#define OFF_AH 0
#define OFF_AL A_SPLIT
#define OFF_BH (2 * A_SPLIT)
#define OFF_BL (2 * A_SPLIT + B_SPLIT)
#define STAGE_BYTES (2 * A_SPLIT + 2 * B_SPLIT)  // 55296
#define DYN_BYTES (2 * STAGE_BYTES)              // 110592
#define PATCH_STRIDE 68                          // floats; 272B row
#define PATCH_BYTES (32 * PATCH_STRIDE * 4)      // 8704; x4 warps = 34816

__device__ __forceinline__ void cpa16(uint32_t dst, const void* src) {
    asm volatile("cp.async.cg.shared.global [%0], [%1], 16;" :: "r"(dst), "l"(src));
}
#define CP_COMMIT() asm volatile("cp.async.commit_group;" ::: "memory")
#define CP_WAIT1()  asm volatile("cp.async.wait_group 1;" ::: "memory")

__device__ __forceinline__ void mma16816(float* c, const uint32_t* a, uint32_t b0, uint32_t b1) {
    asm volatile(
        "mma.sync.aligned.m16n8k16.row.col.f32.bf16.bf16.f32 "
        "{%0,%1,%2,%3}, {%4,%5,%6,%7}, {%8,%9}, {%0,%1,%2,%3};"
        : "+f"(c[0]), "+f"(c[1]), "+f"(c[2]), "+f"(c[3])
        : "r"(a[0]), "r"(a[1]), "r"(a[2]), "r"(a[3]), "r"(b0), "r"(b1));
}

__global__ __launch_bounds__(128, 2)
void gemm_fused(const float* __restrict__ h_ext, int first, int NC, int cur, int nxt) {
    extern __shared__ char dyn[];
    __shared__ float sbias[128];

    // resolve scratch pointers IN DEVICE CODE (host-side symbol refs are UB)
    const __nv_bfloat16 *Ah, *Al, *Bh, *Bl;
    if (first)         { Ah = g_Ah0; Al = g_Al0; Bh = g_W0h; Bl = g_W0l; }
    else if (cur == 0) { Ah = g_Xh0; Al = g_Xl0; Bh = g_Wh2; Bl = g_Wl2; }
    else               { Ah = g_Xh1; Al = g_Xl1; Bh = g_Wh2; Bl = g_Wl2; }
    __nv_bfloat16* XhO = nxt ? g_Xh1 : g_Xh0;
    __nv_bfloat16* XlO = nxt ? g_Xl1 : g_Xl0;

    const int tid = threadIdx.x, wid = tid >> 5, lane = tid & 31;
    const int g = lane >> 2, t = lane & 3;
    const int bn = blockIdx.x;             // 0..3 (128 reordered cols = 32 channels)
    const int bm = blockIdx.y;             // 0..63
    const int m0 = bm * 64;
    const int wm = (wid >> 1) * 32;        // 2x2 warp grid, warp tile 32x64
    const int wn = (wid & 1) * 64;

    if (tid < 128) sbias[tid] = g_bias2[bn * 128 + tid];

    const int strideK = NC * 64;
    const __nv_bfloat16* Abh = Ah + (size_t)m0 * strideK;
    const __nv_bfloat16* Abl = Al + (size_t)m0 * strideK;
    const __nv_bfloat16* Bbh = Bh + (size_t)(bn * 128) * strideK;
    const __nv_bfloat16* Bbl = Bl + (size_t)(bn * 128) * strideK;

    const uint32_t sbase = (uint32_t)__cvta_generic_to_shared(dyn);

    // issue one K-chunk into stage s (async)
    auto issue_chunk = [&](int cch, int s) {
        uint32_t st = sbase + s * STAGE_BYTES;
#pragma unroll
        for (int i = tid; i < 512; i += 128) {       // A: 64 rows x 8 segs
            int row = i >> 3, seg = i & 7;
            uint32_t dst = row * 144 + seg * 16;
            size_t src = (size_t)row * strideK + cch * 64 + seg * 8;
            cpa16(st + OFF_AH + dst, Abh + src);
            cpa16(st + OFF_AL + dst, Abl + src);
        }
#pragma unroll
        for (int i = tid; i < 1024; i += 128) {      // B: 128 rows x 8 segs
            int row = i >> 3, seg = i & 7;
            uint32_t dst = row * 144 + seg * 16;
            size_t src = (size_t)row * strideK + cch * 64 + seg * 8;
            cpa16(st + OFF_BH + dst, Bbh + src);
            cpa16(st + OFF_BL + dst, Bbl + src);
        }
    };

    issue_chunk(0, 0); CP_COMMIT();
    if (NC > 1) issue_chunk(1, 1);
    CP_COMMIT();

    float acc[2][8][4];
#pragma unroll
    for (int mi = 0; mi < 2; mi++)
#pragma unroll
        for (int ni = 0; ni < 8; ni++)
#pragma unroll
            for (int e = 0; e < 4; e++) acc[mi][ni][e] = 0.0f;

    for (int c = 0; c < NC; c++) {
        CP_WAIT1();                 // chunk c's group complete (all but newest)
        __syncthreads();
        const char* st = dyn + (c & 1) * STAGE_BYTES;

#pragma unroll
        for (int ks = 0; ks < 4; ks++) {
            uint32_t ah[2][4], al[2][4];
            const int kb = ks * 32 + t * 4;
#pragma unroll
            for (int mi = 0; mi < 2; mi++) {
                int r0 = (wm + mi * 16 + g) * 144 + kb;
                int r1 = r0 + 8 * 144;
                ah[mi][0] = *(const uint32_t*)(st + OFF_AH + r0);
                ah[mi][1] = *(const uint32_t*)(st + OFF_AH + r1);
                ah[mi][2] = *(const uint32_t*)(st + OFF_AH + r0 + 16);
                ah[mi][3] = *(const uint32_t*)(st + OFF_AH + r1 + 16);
                al[mi][0] = *(const uint32_t*)(st + OFF_AL + r0);
                al[mi][1] = *(const uint32_t*)(st + OFF_AL + r1);
                al[mi][2] = *(const uint32_t*)(st + OFF_AL + r0 + 16);
                al[mi][3] = *(const uint32_t*)(st + OFF_AL + r1 + 16);
            }
#pragma unroll
            for (int ni = 0; ni < 8; ni++) {
                int nrow = (wn + ni * 8 + g) * 144 + kb;
                uint32_t bh0 = *(const uint32_t*)(st + OFF_BH + nrow);
                uint32_t bh1 = *(const uint32_t*)(st + OFF_BH + nrow + 16);
                uint32_t bl0 = *(const uint32_t*)(st + OFF_BL + nrow);
                uint32_t bl1 = *(const uint32_t*)(st + OFF_BL + nrow + 16);
#pragma unroll
                for (int mi = 0; mi < 2; mi++) {
                    mma16816(acc[mi][ni], ah[mi], bh0, bh1);
                    mma16816(acc[mi][ni], al[mi], bh0, bh1);
                    mma16816(acc[mi][ni], ah[mi], bl0, bl1);
                }
            }
        }
        __syncthreads();            // all warps done with stage (c&1)
        if (c + 2 < NC) issue_chunk(c + 2, c & 1);
        CP_COMMIT();                // commit (possibly empty) to keep counts aligned
    }

    // ---- dump acc to per-warp patch [32][68] floats ----
    float* patch = (float*)(dyn + wid * PATCH_BYTES);
#pragma unroll
    for (int mi = 0; mi < 2; mi++)
#pragma unroll
        for (int ni = 0; ni < 8; ni++) {
            int pr = mi * 16 + g, pc = ni * 8 + 2 * t;
            *(float2*)&patch[pr * PATCH_STRIDE + pc]       = make_float2(acc[mi][ni][0], acc[mi][ni][1]);
            *(float2*)&patch[(pr + 8) * PATCH_STRIDE + pc] = make_float2(acc[mi][ni][2], acc[mi][ni][3]);
        }
    __syncthreads();

    // ---- fused LSTM: 64 rows x 32 channels per CTA = 2048 items ----
#pragma unroll
    for (int it = 0; it < 16; it++) {
        int item = tid + it * 128;
        int r = item >> 5, chl = item & 31;
        int w = (r >> 5) * 2 + (chl >> 4);    // source warp patch
        const float* p = (const float*)(dyn + w * PATCH_BYTES)
                         + (r & 31) * PATCH_STRIDE + (chl & 15) * 4;
        float4 gv = *(const float4*)p;
        int cb = chl * 4;
        float gi = gv.x + sbias[cb + 0];
        float gf = gv.y + sbias[cb + 1];
        float gg = gv.z + sbias[cb + 2];
        float go = gv.w + sbias[cb + 3];
        int row = m0 + r;
        int ch = bn * 32 + chl;
        size_t cidx = (size_t)row * C + ch;
        float cp = first ? h_ext[cidx] : g_c[cidx];
        float cn = sigf(gf) * cp + sigf(gi) * tanhf(gg);
        g_c[cidx] = cn;
        float hn = sigf(go) * tanhf(cn);
        g_q[cidx] = hn;
        __nv_bfloat16 hh = __float2bfloat16(hn);
        XhO[(size_t)row * 256 + ch] = hh;
        XlO[(size_t)row * 256 + ch] = __float2bfloat16(hn - __bfloat162float(hh));
    }
}

// ---------------- segment attention: one block per segment ------------------
__global__ __launch_bounds__(256)
void attn_kernel(const float* __restrict__ kmat, const float* __restrict__ vmat,
                 float* __restrict__ out, int iter, int nxt) {
    int b = blockIdx.x;
    int tid = threadIdx.x;
    int lane = tid & 31;
    int w = tid >> 5;                       // 8 warps
    int start = g_seg[b], end = g_seg[b + 1];

    __nv_bfloat16* XhO = nxt ? g_Xh1 : g_Xh0;
    __nv_bfloat16* XlO = nxt ? g_Xl1 : g_Xl0;

    float4 q4 = *(const float4*)(g_q + (size_t)b * C + lane * 4);

    __shared__ float smax[8];
    __shared__ float ssum[8];
    __shared__ __align__(16) float sr[8][C];

    // pass 1: logits + max
    float wmax = -INFINITY;
    int node = start + w;
    for (; node + 8 < end; node += 16) {
        float4 ka = *(const float4*)(kmat + (size_t)node * C + lane * 4);
        float4 kb = *(const float4*)(kmat + (size_t)(node + 8) * C + lane * 4);
        float da = ka.x * q4.x + ka.y * q4.y + ka.z * q4.z + ka.w * q4.w;
        float db = kb.x * q4.x + kb.y * q4.y + kb.z * q4.z + kb.w * q4.w;
#pragma unroll
        for (int off = 16; off > 0; off >>= 1) {
            da += __shfl_xor_sync(0xFFFFFFFFu, da, off);
            db += __shfl_xor_sync(0xFFFFFFFFu, db, off);
        }
        if (lane == 0) { g_e[node] = da; g_e[node + 8] = db; }
        wmax = fmaxf(wmax, fmaxf(da, db));
    }
    for (; node < end; node += 8) {
        float4 ka = *(const float4*)(kmat + (size_t)node * C + lane * 4);
        float da = ka.x * q4.x + ka.y * q4.y + ka.z * q4.z + ka.w * q4.w;
#pragma unroll
        for (int off = 16; off > 0; off >>= 1)
            da += __shfl_xor_sync(0xFFFFFFFFu, da, off);
        if (lane == 0) g_e[node] = da;
        wmax = fmaxf(wmax, da);
    }
    if (lane == 0) smax[w] = wmax;
    __syncthreads();

    float m = -INFINITY;
#pragma unroll
    for (int i = 0; i < 8; i++) m = fmaxf(m, smax[i]);

    // pass 2: exp + weighted V sum
    float s = 0.0f;
    float4 r4 = make_float4(0.f, 0.f, 0.f, 0.f);
    for (node = start + w; node < end; node += 8) {
        float a = __expf(g_e[node] - m);
        float4 v4 = *(const float4*)(vmat + (size_t)node * C + lane * 4);
        s += a;
        r4.x = fmaf(a, v4.x, r4.x); r4.y = fmaf(a, v4.y, r4.y);
        r4.z = fmaf(a, v4.z, r4.z); r4.w = fmaf(a, v4.w, r4.w);
    }
    if (lane == 0) ssum[w] = s;
    *(float4*)(&sr[w][lane * 4]) = r4;
    __syncthreads();

    if (tid < C) {
        float stot = 0.0f, rc = 0.0f;
#pragma unroll
        for (int i = 0; i < 8; i++) { stot += ssum[i]; rc += sr[i][tid]; }
        float val = rc / (stot + 1e-16f);
        out[(size_t)b * 4 * C + iter * C + tid] = val;       // readout
        __nv_bfloat16 hv = __float2bfloat16(val);            // r splits for next GEMM
        XhO[(size_t)b * 256 + C + tid] = hv;
        XlO[(size_t)b * 256 + C + tid] = __float2bfloat16(val - __bfloat162float(hv));
    }
}

// ---------------- launch -----------------------------------------------------
extern "C" void kernel_launch(void* const* d_in, const int* in_sizes, int n_in,
                              void* d_out, int out_size) {
    const float* k     = (const float*)d_in[0];
    const float* v     = (const float*)d_in[1];
    const float* h     = (const float*)d_in[2];
    const float* W_ih  = (const float*)d_in[3];
    const float* W_hh  = (const float*)d_in[4];
    const float* b_ih  = (const float*)d_in[5];
    const float* b_hh  = (const float*)d_in[6];
    const int*   batch = (const int*)d_in[7];
    float* out = (float*)d_out;

    int N = in_sizes[0] / C;
    int B = in_sizes[2] / C;

    cudaFuncSetAttribute(gemm_fused, cudaFuncAttributeMaxDynamicSharedMemorySize, DYN_BYTES);

    int prep_items = (B * C > N + 1) ? B * C : N + 1;   // covers 512*256 too
    prep_all<<<(prep_items + 255) / 256, 256>>>(W_ih, W_hh, b_ih, b_hh, h, batch, N, B);

    for (int t = 0; t < 4; t++) {
        int cur = t & 1, nxt = (t + 1) & 1;
        gemm_fused<<<dim3(4, B / 64), 128, DYN_BYTES>>>(
            h, t == 0 ? 1 : 0, t == 0 ? 2 : 4, cur, nxt);
        attn_kernel<<<B, 256>>>(k, v, out, t, nxt);
    }
}